// round 1
// baseline (speedup 1.0000x reference)
#include <cuda_runtime.h>

#define NGRID    8192
#define NLAYER   24
#define NPERIODS 50
#define NOBS     4096
#define NC       200
#define NPAD     64      // pad period dim 50 -> 64 for clean float4 tiling

#define BM 64
#define BN 64
#define BK 16
#define SPLITK 4

// Scratch (no allocations allowed -> __device__ globals)
__device__ float  g_W[NPERIODS * NLAYER];     // (P, L) normalized weights
__device__ float  g_rcp[NGRID * NPAD];        // 1/c_true, padded cols = 0
__device__ float  g_spred[NOBS * NPAD];       // A @ rcp (padded cols = 0)
__device__ double g_acc;                      // sum of (e_max - e_interp)

// ---------------------------------------------------------------- zero
__global__ void k_zero() {
    int idx = blockIdx.x * blockDim.x + threadIdx.x;
    int n = NOBS * NPAD;
    for (int i = idx; i < n; i += gridDim.x * blockDim.x) g_spred[i] = 0.0f;
    if (idx == 0) g_acc = 0.0;
}

// ---------------------------------------------------------------- weights
__global__ void k_weights(const float* __restrict__ thick,
                          const float* __restrict__ periods) {
    int p = threadIdx.x;
    if (p >= NPERIODS) return;
    float th[NLAYER], z[NLAYER];
    float cs = 0.0f;
    for (int l = 0; l < NLAYER; l++) {
        th[l] = thick[l];
        cs += th[l];
        z[l] = cs - 0.5f * th[l];
    }
    // depth_scale = VREF * period / 3.0, VREF = 3.0
    float ds = 3.0f * periods[p] / 3.0f;
    float inv_ds = 1.0f / ds;
    float w[NLAYER];
    float s = 0.0f;
    for (int l = 0; l < NLAYER; l++) {
        w[l] = expf(-z[l] * inv_ds) * th[l];
        s += w[l];
    }
    float inv_s = 1.0f / s;
    for (int l = 0; l < NLAYER; l++)
        g_W[p * NLAYER + l] = w[l] * inv_s;
}

// ---------------------------------------------------------------- rcp = 1/c_true
__global__ void k_rcp(const float* __restrict__ Vs) {
    int idx = blockIdx.x * blockDim.x + threadIdx.x;
    if (idx >= NGRID * NPAD) return;
    int g = idx >> 6;
    int c = idx & 63;
    float v = 0.0f;
    if (c < NPERIODS) {
        const float* vs = Vs + g * NLAYER;
        const float* w  = g_W + c * NLAYER;
        float s = 0.0f;
#pragma unroll
        for (int l = 0; l < NLAYER; l++) s += w[l] * vs[l];
        v = 1.0f / (0.92f * s);
    }
    g_rcp[idx] = v;
}

// ---------------------------------------------------------------- GEMM: s_pred = A @ rcp
// A: (NOBS, NGRID) row-major.  B = g_rcp: (NGRID, NPAD) row-major.
// grid = (NOBS/BM, SPLITK), 256 threads, each thread computes 4x4 outputs.
__global__ void __launch_bounds__(256) k_gemm(const float* __restrict__ A) {
    __shared__ __align__(16) float As[BK][BM + 4];   // +4 pad: 272B rows keep 16B align, cut store conflicts
    __shared__ __align__(16) float Bs[BK][BN];

    int tid = threadIdx.x;
    int tx = tid & 15;        // col group
    int ty = tid >> 4;        // row group
    int row0 = blockIdx.x * BM;
    int kChunk = NGRID / SPLITK;
    int k0   = blockIdx.y * kChunk;
    int kEnd = k0 + kChunk;

    int aK = tid & 15;        // k within tile for A loads
    int aM = tid >> 4;        // base m for A loads

    float acc[4][4] = {};

    for (int kt = k0; kt < kEnd; kt += BK) {
        // A tile: 64x16, coalesced 64B row segments
#pragma unroll
        for (int p = 0; p < 4; p++) {
            int m = aM + p * 16;
            As[aK][m] = A[(size_t)(row0 + m) * NGRID + kt + aK];
        }
        // B tile: 16 full contiguous rows of g_rcp -> perfectly coalesced float4
        const float4* bsrc = (const float4*)(g_rcp + (size_t)kt * NPAD);
        ((float4*)&Bs[0][0])[tid] = bsrc[tid];
        __syncthreads();

#pragma unroll
        for (int kk = 0; kk < BK; kk++) {
            float4 a = *(const float4*)&As[kk][ty * 4];
            float4 b = *(const float4*)&Bs[kk][tx * 4];
            acc[0][0] += a.x * b.x; acc[0][1] += a.x * b.y; acc[0][2] += a.x * b.z; acc[0][3] += a.x * b.w;
            acc[1][0] += a.y * b.x; acc[1][1] += a.y * b.y; acc[1][2] += a.y * b.z; acc[1][3] += a.y * b.w;
            acc[2][0] += a.z * b.x; acc[2][1] += a.z * b.y; acc[2][2] += a.z * b.z; acc[2][3] += a.z * b.w;
            acc[3][0] += a.w * b.x; acc[3][1] += a.w * b.y; acc[3][2] += a.w * b.z; acc[3][3] += a.w * b.w;
        }
        __syncthreads();
    }

#pragma unroll
    for (int i = 0; i < 4; i++)
#pragma unroll
        for (int j = 0; j < 4; j++)
            atomicAdd(&g_spred[(size_t)(row0 + ty * 4 + i) * NPAD + tx * 4 + j], acc[i][j]);
}

// ---------------------------------------------------------------- epilogue
// One warp per (obs, period): max over 200 energies + searchsorted interp.
__global__ void __launch_bounds__(256) k_epilogue(const float* __restrict__ energy,
                                                  const float* __restrict__ c_axis) {
    int lane = threadIdx.x & 31;
    int warp = blockIdx.x * (blockDim.x >> 5) + (threadIdx.x >> 5);
    int totalWarps = gridDim.x * (blockDim.x >> 5);

    float wsum = 0.0f;
    for (int pair = warp; pair < NOBS * NPERIODS; pair += totalWarps) {
        int obs = pair / NPERIODS;
        const float* e = energy + (size_t)pair * NC;

        float m = -1e30f;
        for (int i = lane; i < NC; i += 32) m = fmaxf(m, e[i]);
#pragma unroll
        for (int o = 16; o; o >>= 1) m = fmaxf(m, __shfl_xor_sync(0xffffffffu, m, o));

        if (lane == 0) {
            int p = pair - obs * NPERIODS;
            float s  = g_spred[(size_t)obs * NPAD + p];
            float cp = 1.0f / s;
            const float* ca = c_axis + (size_t)obs * NC;
            // searchsorted side='left': first idx with ca[idx] >= cp
            int lo = 0, hi = NC;
            while (lo < hi) {
                int mid = (lo + hi) >> 1;
                if (ca[mid] < cp) lo = mid + 1; else hi = mid;
            }
            int idx = lo;
            if (idx < 1) idx = 1;
            if (idx > NC - 1) idx = NC - 1;
            float c0 = ca[idx - 1], c1 = ca[idx];
            float e0 = e[idx - 1],  e1 = e[idx];
            float w = (cp - c0) / (c1 - c0 + 1e-12f);
            float ei = e0 + w * (e1 - e0);
            wsum += m - ei;
        }
    }

    __shared__ float part[8];
    if (lane == 0) part[threadIdx.x >> 5] = wsum;
    __syncthreads();
    if (threadIdx.x == 0) {
        float s = 0.0f;
        for (int i = 0; i < (int)(blockDim.x >> 5); i++) s += part[i];
        atomicAdd(&g_acc, (double)s);
    }
}

// ---------------------------------------------------------------- final scalar
__global__ void k_out(float* out) {
    out[0] = (float)(-g_acc);   // SIGMA = 1.0
}

// ---------------------------------------------------------------- launch
extern "C" void kernel_launch(void* const* d_in, const int* in_sizes, int n_in,
                              void* d_out, int out_size) {
    // Resolve inputs by element count (all sizes distinct) — robust to ordering.
    const float *Vs = nullptr, *A = nullptr, *energy = nullptr,
                *c_axis = nullptr, *thick = nullptr, *periods = nullptr;
    for (int i = 0; i < n_in; i++) {
        switch (in_sizes[i]) {
            case NGRID * NLAYER:          Vs      = (const float*)d_in[i]; break;
            case NOBS * NGRID:            A       = (const float*)d_in[i]; break;
            case NOBS * NPERIODS * NC:    energy  = (const float*)d_in[i]; break;
            case NOBS * NC:               c_axis  = (const float*)d_in[i]; break;
            case NLAYER:                  thick   = (const float*)d_in[i]; break;
            case NPERIODS:                periods = (const float*)d_in[i]; break;
        }
    }

    k_zero<<<256, 256>>>();
    k_weights<<<1, 64>>>(thick, periods);
    k_rcp<<<(NGRID * NPAD + 255) / 256, 256>>>(Vs);

    dim3 g(NOBS / BM, SPLITK);
    k_gemm<<<g, 256>>>(A);

    k_epilogue<<<1184, 256>>>(energy, c_axis);
    k_out<<<1, 1>>>((float*)d_out);
}

// round 2
// speedup vs baseline: 1.9876x; 1.9876x over previous
#include <cuda_runtime.h>
#include <cuda_bf16.h>
#include <stdint.h>

#define NGRID    8192
#define NLAYER   24
#define NPERIODS 50
#define NOBS     4096
#define NC       200
#define NPAD     64

#define BM       128
#define SPLITK   8

// Scratch (no allocations allowed -> __device__ globals)
__device__ float          g_W[NPERIODS * NLAYER];      // (P, L) normalized weights
__device__ __nv_bfloat16  g_rcpBT[NPAD * NGRID];       // B^T: [n][k], pad rows = 0
__device__ float          g_spred[NOBS * NPAD];        // A @ rcp (fp32 accum)
__device__ double         g_acc;                       // sum of (e_max - e_interp)

// ---------------------------------------------------------------- zero
__global__ void k_zero() {
    int idx = blockIdx.x * blockDim.x + threadIdx.x;
    int n = NOBS * NPAD;
    for (int i = idx; i < n; i += gridDim.x * blockDim.x) g_spred[i] = 0.0f;
    if (idx == 0) g_acc = 0.0;
}

// ---------------------------------------------------------------- weights
__global__ void k_weights(const float* __restrict__ thick,
                          const float* __restrict__ periods) {
    int p = threadIdx.x;
    if (p >= NPERIODS) return;
    float th[NLAYER], z[NLAYER];
    float cs = 0.0f;
    for (int l = 0; l < NLAYER; l++) {
        th[l] = thick[l];
        cs += th[l];
        z[l] = cs - 0.5f * th[l];
    }
    float ds = 3.0f * periods[p] / 3.0f;   // VREF=3.0
    float inv_ds = 1.0f / ds;
    float w[NLAYER];
    float s = 0.0f;
    for (int l = 0; l < NLAYER; l++) {
        w[l] = expf(-z[l] * inv_ds) * th[l];
        s += w[l];
    }
    float inv_s = 1.0f / s;
    for (int l = 0; l < NLAYER; l++)
        g_W[p * NLAYER + l] = w[l] * inv_s;
}

// ---------------------------------------------------------------- rcp -> B^T (bf16)
// One thread per grid cell: computes all periods, writes BT coalesced along k(=cell).
__global__ void __launch_bounds__(256) k_rcp(const float* __restrict__ Vs) {
    __shared__ float Wsh[NPERIODS * NLAYER];
    for (int i = threadIdx.x; i < NPERIODS * NLAYER; i += 256) Wsh[i] = g_W[i];
    __syncthreads();

    int gcell = blockIdx.x * 256 + threadIdx.x;
    if (gcell >= NGRID) return;

    float v[NLAYER];
    const float4* vp = (const float4*)(Vs + (size_t)gcell * NLAYER);  // 24 floats = 6 float4, 16B aligned
#pragma unroll
    for (int i = 0; i < 6; i++) {
        float4 f = vp[i];
        v[4*i+0] = f.x; v[4*i+1] = f.y; v[4*i+2] = f.z; v[4*i+3] = f.w;
    }
    for (int p = 0; p < NPAD; p++) {
        __nv_bfloat16 out = __float2bfloat16(0.0f);
        if (p < NPERIODS) {
            const float* w = Wsh + p * NLAYER;
            float s = 0.0f;
#pragma unroll
            for (int l = 0; l < NLAYER; l++) s += w[l] * v[l];
            out = __float2bfloat16(1.0f / (0.92f * s));
        }
        g_rcpBT[(size_t)p * NGRID + gcell] = out;
    }
}

// ---------------------------------------------------------------- GEMM (bf16 tensor cores)
// s_pred(4096x64) = A(4096x8192,f32) @ rcp(8192x64,bf16 via BT).
// 8 warps: 4(m) x 2(n); warp tile 32x32 = 2 m16 tiles x 4 n8 tiles; k-step 16.
// A fragments loaded directly from global as 8B f32 pairs -> cvt bf16x2.
// B fragments loaded directly from BT[n][k] (L2-resident, 1MB).
__device__ __forceinline__ uint32_t bf2(float2 f) {
    __nv_bfloat162 h = __float22bfloat162_rn(f);
    return *reinterpret_cast<uint32_t*>(&h);
}

__global__ void __launch_bounds__(256) k_gemm(const float* __restrict__ A) {
    int tid  = threadIdx.x;
    int lane = tid & 31, warp = tid >> 5;
    int wm = warp & 3, wn = warp >> 2;
    int g = lane >> 2, t = lane & 3;
    int m0 = blockIdx.x * BM + wm * 32;
    int n0 = wn * 32;
    const int kChunk = NGRID / SPLITK;     // 1024
    int k0 = blockIdx.y * kChunk;
    int kEnd = k0 + kChunk;

    float acc[2][4][4];
#pragma unroll
    for (int mt = 0; mt < 2; mt++)
#pragma unroll
        for (int nt = 0; nt < 4; nt++)
#pragma unroll
            for (int i = 0; i < 4; i++) acc[mt][nt][i] = 0.0f;

#pragma unroll 2
    for (int k = k0; k < kEnd; k += 16) {
        uint32_t b[4][2];
#pragma unroll
        for (int nt = 0; nt < 4; nt++) {
            const uint32_t* bp = (const uint32_t*)(g_rcpBT + (size_t)(n0 + nt * 8 + g) * NGRID + k);
            b[nt][0] = bp[t];       // k = k+2t, k+2t+1
            b[nt][1] = bp[t + 4];   // k = k+8+2t, +1
        }
#pragma unroll
        for (int mt = 0; mt < 2; mt++) {
            const float* ar = A + (size_t)(m0 + mt * 16 + g) * NGRID + k + t * 2;
            float2 f0 = *(const float2*)ar;
            float2 f1 = *(const float2*)(ar + (size_t)8 * NGRID);
            float2 f2 = *(const float2*)(ar + 8);
            float2 f3 = *(const float2*)(ar + (size_t)8 * NGRID + 8);
            uint32_t a0 = bf2(f0), a1 = bf2(f1), a2 = bf2(f2), a3 = bf2(f3);
#pragma unroll
            for (int nt = 0; nt < 4; nt++) {
                asm volatile(
                    "mma.sync.aligned.m16n8k16.row.col.f32.bf16.bf16.f32 "
                    "{%0,%1,%2,%3}, {%4,%5,%6,%7}, {%8,%9}, {%0,%1,%2,%3};\n"
                    : "+f"(acc[mt][nt][0]), "+f"(acc[mt][nt][1]),
                      "+f"(acc[mt][nt][2]), "+f"(acc[mt][nt][3])
                    : "r"(a0), "r"(a1), "r"(a2), "r"(a3),
                      "r"(b[nt][0]), "r"(b[nt][1]));
            }
        }
    }

#pragma unroll
    for (int mt = 0; mt < 2; mt++)
#pragma unroll
        for (int nt = 0; nt < 4; nt++) {
            int r0 = m0 + mt * 16 + g;
            int c  = n0 + nt * 8 + t * 2;
            atomicAdd(&g_spred[(size_t)r0 * NPAD + c],           acc[mt][nt][0]);
            atomicAdd(&g_spred[(size_t)r0 * NPAD + c + 1],       acc[mt][nt][1]);
            atomicAdd(&g_spred[(size_t)(r0 + 8) * NPAD + c],     acc[mt][nt][2]);
            atomicAdd(&g_spred[(size_t)(r0 + 8) * NPAD + c + 1], acc[mt][nt][3]);
        }
}

// ---------------------------------------------------------------- epilogue
// One warp per (obs, period). float4 loads; searchsorted via warp-parallel count
// (idx = #{ca < cp}, sorted axis), REDUX sum; lane0 does the 4-element gather (L1-hot).
__global__ void __launch_bounds__(256) k_epilogue(const float* __restrict__ energy,
                                                  const float* __restrict__ c_axis) {
    int lane = threadIdx.x & 31;
    int warpId = (blockIdx.x * blockDim.x + threadIdx.x) >> 5;
    int nWarps = (gridDim.x * blockDim.x) >> 5;

    float wsum = 0.0f;
    for (int pair = warpId; pair < NOBS * NPERIODS; pair += nWarps) {
        int obs = pair / NPERIODS;
        int p   = pair - obs * NPERIODS;

        const float4* e4 = (const float4*)(energy + (size_t)pair * NC);  // 50 float4
        float4 v = e4[lane];
        float m = fmaxf(fmaxf(v.x, v.y), fmaxf(v.z, v.w));
        if (lane < 18) {
            float4 v2 = e4[lane + 32];
            m = fmaxf(m, fmaxf(fmaxf(v2.x, v2.y), fmaxf(v2.z, v2.w)));
        }
#pragma unroll
        for (int o = 16; o; o >>= 1) m = fmaxf(m, __shfl_xor_sync(0xffffffffu, m, o));

        float cp = 1.0f / g_spred[(size_t)obs * NPAD + p];   // broadcast load

        const float4* ca4 = (const float4*)(c_axis + (size_t)obs * NC);
        float4 c = ca4[lane];
        int cnt = (c.x < cp) + (c.y < cp) + (c.z < cp) + (c.w < cp);
        if (lane < 18) {
            float4 c2 = ca4[lane + 32];
            cnt += (c2.x < cp) + (c2.y < cp) + (c2.z < cp) + (c2.w < cp);
        }
        int idx = __reduce_add_sync(0xffffffffu, cnt);       // searchsorted-left
        idx = min(max(idx, 1), NC - 1);

        if (lane == 0) {
            const float* ca = c_axis + (size_t)obs * NC;
            const float* e  = energy + (size_t)pair * NC;
            float c0 = ca[idx - 1], c1 = ca[idx];
            float e0 = e[idx - 1],  e1 = e[idx];
            float w = (cp - c0) / (c1 - c0 + 1e-12f);
            wsum += m - (e0 + w * (e1 - e0));
        }
    }

    __shared__ float part[8];
    if (lane == 0) part[threadIdx.x >> 5] = wsum;
    __syncthreads();
    if (threadIdx.x == 0) {
        float s = 0.0f;
        for (int i = 0; i < 8; i++) s += part[i];
        atomicAdd(&g_acc, (double)s);
    }
}

// ---------------------------------------------------------------- final scalar
__global__ void k_out(float* out) {
    out[0] = (float)(-g_acc);   // SIGMA = 1.0
}

// ---------------------------------------------------------------- launch
extern "C" void kernel_launch(void* const* d_in, const int* in_sizes, int n_in,
                              void* d_out, int out_size) {
    const float *Vs = nullptr, *A = nullptr, *energy = nullptr,
                *c_axis = nullptr, *thick = nullptr, *periods = nullptr;
    for (int i = 0; i < n_in; i++) {
        switch (in_sizes[i]) {
            case NGRID * NLAYER:          Vs      = (const float*)d_in[i]; break;
            case NOBS * NGRID:            A       = (const float*)d_in[i]; break;
            case NOBS * NPERIODS * NC:    energy  = (const float*)d_in[i]; break;
            case NOBS * NC:               c_axis  = (const float*)d_in[i]; break;
            case NLAYER:                  thick   = (const float*)d_in[i]; break;
            case NPERIODS:                periods = (const float*)d_in[i]; break;
        }
    }

    k_zero<<<256, 256>>>();
    k_weights<<<1, 64>>>(thick, periods);
    k_rcp<<<NGRID / 256, 256>>>(Vs);

    dim3 g(NOBS / BM, SPLITK);
    k_gemm<<<g, 256>>>(A);

    k_epilogue<<<2048, 256>>>(energy, c_axis);
    k_out<<<1, 1>>>((float*)d_out);
}

// round 3
// speedup vs baseline: 3.0248x; 1.5219x over previous
#include <cuda_runtime.h>
#include <cuda_bf16.h>
#include <stdint.h>

#define NGRID    8192
#define NLAYER   24
#define NPERIODS 50
#define NOBS     4096
#define NC       200
#define NPAD     64

#define BM       128
#define BN       64
#define BK       64
#define SPLITK   16
#define KCHUNK   (NGRID / SPLITK)    // 512

// Scratch (no allocations allowed -> __device__ globals)
__device__ float                       g_W[NPERIODS * NLAYER];
__device__ __align__(16) __nv_bfloat16 g_rcpBT[NPAD * NGRID];     // B^T: [n][k]
__device__ __align__(16) float         g_part[SPLITK][NOBS * NPAD];
__device__ __align__(16) float         g_spred[NOBS * NPAD];
__device__ double                      g_acc;

// ---------------------------------------------------------------- zero (g_acc only)
__global__ void k_zero() { g_acc = 0.0; }

// ---------------------------------------------------------------- weights
__global__ void k_weights(const float* __restrict__ thick,
                          const float* __restrict__ periods) {
    int p = threadIdx.x;
    if (p >= NPERIODS) return;
    float th[NLAYER], z[NLAYER];
    float cs = 0.0f;
    for (int l = 0; l < NLAYER; l++) {
        th[l] = thick[l];
        cs += th[l];
        z[l] = cs - 0.5f * th[l];
    }
    float ds = 3.0f * periods[p] / 3.0f;   // VREF=3.0
    float inv_ds = 1.0f / ds;
    float w[NLAYER];
    float s = 0.0f;
    for (int l = 0; l < NLAYER; l++) {
        w[l] = expf(-z[l] * inv_ds) * th[l];
        s += w[l];
    }
    float inv_s = 1.0f / s;
    for (int l = 0; l < NLAYER; l++)
        g_W[p * NLAYER + l] = w[l] * inv_s;
}

// ---------------------------------------------------------------- rcp -> B^T (bf16)
__global__ void __launch_bounds__(256) k_rcp(const float* __restrict__ Vs) {
    __shared__ float Wsh[NPERIODS * NLAYER];
    for (int i = threadIdx.x; i < NPERIODS * NLAYER; i += 256) Wsh[i] = g_W[i];
    __syncthreads();

    int gcell = blockIdx.x * 256 + threadIdx.x;
    if (gcell >= NGRID) return;

    float v[NLAYER];
    const float4* vp = (const float4*)(Vs + (size_t)gcell * NLAYER);
#pragma unroll
    for (int i = 0; i < 6; i++) {
        float4 f = vp[i];
        v[4*i+0] = f.x; v[4*i+1] = f.y; v[4*i+2] = f.z; v[4*i+3] = f.w;
    }
    for (int p = 0; p < NPAD; p++) {
        __nv_bfloat16 out = __float2bfloat16(0.0f);
        if (p < NPERIODS) {
            const float* w = Wsh + p * NLAYER;
            float s = 0.0f;
#pragma unroll
            for (int l = 0; l < NLAYER; l++) s += w[l] * v[l];
            out = __float2bfloat16(1.0f / (0.92f * s));
        }
        g_rcpBT[(size_t)p * NGRID + gcell] = out;   // coalesced along gcell
    }
}

// ---------------------------------------------------------------- GEMM (bf16 HMMA, smem-staged)
// grid = (NOBS/BM, SPLITK). Block computes BM x 64 over KCHUNK, writes partials.
__global__ void __launch_bounds__(256, 2) k_gemm(const float* __restrict__ A) {
    __shared__ __align__(16) __nv_bfloat16 As[BM][BK + 8];   // stride 72 -> (4g+t)%32 conflict-free
    __shared__ __align__(16) __nv_bfloat16 Bs[BN][BK + 8];

    int tid  = threadIdx.x;
    int lane = tid & 31, warp = tid >> 5;
    int wm = warp & 3, wn = warp >> 2;          // 4 x 2 warp grid
    int g = lane >> 2, t = lane & 3;
    int mBase = blockIdx.x * BM;
    int kt0   = blockIdx.y * KCHUNK;

    float acc[2][4][4];
#pragma unroll
    for (int mt = 0; mt < 2; mt++)
#pragma unroll
        for (int nt = 0; nt < 4; nt++)
#pragma unroll
            for (int i = 0; i < 4; i++) acc[mt][nt][i] = 0.0f;

    float4 aR[8], bR[2];

    // coalesced tile prefetch into registers
    int aRow = 0, aC4 = 0;   // (compiler folds these)
#define LOAD_A(KT)                                                              \
    _Pragma("unroll")                                                           \
    for (int i = 0; i < 8; i++) {                                               \
        int f = i * 256 + tid; int row = f >> 4; int c4 = f & 15;               \
        aR[i] = *(const float4*)(A + (size_t)(mBase + row) * NGRID + (KT) + c4 * 4); \
    }
#define LOAD_B(KT)                                                              \
    _Pragma("unroll")                                                           \
    for (int i = 0; i < 2; i++) {                                               \
        int f = i * 256 + tid; int row = f >> 3; int c4 = f & 7;                \
        bR[i] = *(const float4*)((const __nv_bfloat16*)g_rcpBT + (size_t)row * NGRID + (KT) + c4 * 8); \
    }

    LOAD_A(kt0);
    LOAD_B(kt0);

    for (int kt = kt0; kt < kt0 + KCHUNK; kt += BK) {
        // stage registers -> smem (f32 -> bf16 for A)
#pragma unroll
        for (int i = 0; i < 8; i++) {
            int f = i * 256 + tid; int row = f >> 4; int c4 = f & 15;
            __nv_bfloat162 lo = __float22bfloat162_rn(make_float2(aR[i].x, aR[i].y));
            __nv_bfloat162 hi = __float22bfloat162_rn(make_float2(aR[i].z, aR[i].w));
            __nv_bfloat162* dst = (__nv_bfloat162*)&As[row][c4 * 4];
            dst[0] = lo; dst[1] = hi;
        }
#pragma unroll
        for (int i = 0; i < 2; i++) {
            int f = i * 256 + tid; int row = f >> 3; int c4 = f & 7;
            *(float4*)&Bs[row][c4 * 8] = bR[i];
        }
        __syncthreads();

        if (kt + BK < kt0 + KCHUNK) { LOAD_A(kt + BK); LOAD_B(kt + BK); }

#pragma unroll
        for (int kk = 0; kk < BK; kk += 16) {
            uint32_t b[4][2];
#pragma unroll
            for (int nt = 0; nt < 4; nt++) {
                const uint32_t* bp = (const uint32_t*)&Bs[wn * 32 + nt * 8 + g][kk];
                b[nt][0] = bp[t]; b[nt][1] = bp[t + 4];
            }
#pragma unroll
            for (int mt = 0; mt < 2; mt++) {
                int r = wm * 32 + mt * 16 + g;
                const uint32_t* a0p = (const uint32_t*)&As[r][kk];
                const uint32_t* a1p = (const uint32_t*)&As[r + 8][kk];
                uint32_t a0 = a0p[t], a2 = a0p[t + 4];
                uint32_t a1 = a1p[t], a3 = a1p[t + 4];
#pragma unroll
                for (int nt = 0; nt < 4; nt++) {
                    asm volatile(
                        "mma.sync.aligned.m16n8k16.row.col.f32.bf16.bf16.f32 "
                        "{%0,%1,%2,%3}, {%4,%5,%6,%7}, {%8,%9}, {%0,%1,%2,%3};\n"
                        : "+f"(acc[mt][nt][0]), "+f"(acc[mt][nt][1]),
                          "+f"(acc[mt][nt][2]), "+f"(acc[mt][nt][3])
                        : "r"(a0), "r"(a1), "r"(a2), "r"(a3),
                          "r"(b[nt][0]), "r"(b[nt][1]));
                }
            }
        }
        __syncthreads();
    }

    // non-atomic split-K partials
    float* out = g_part[blockIdx.y];
#pragma unroll
    for (int mt = 0; mt < 2; mt++)
#pragma unroll
        for (int nt = 0; nt < 4; nt++) {
            int r0 = mBase + wm * 32 + mt * 16 + g;
            int c  = wn * 32 + nt * 8 + t * 2;
            *(float2*)&out[(size_t)r0 * NPAD + c]       = make_float2(acc[mt][nt][0], acc[mt][nt][1]);
            *(float2*)&out[(size_t)(r0 + 8) * NPAD + c] = make_float2(acc[mt][nt][2], acc[mt][nt][3]);
        }
}

// ---------------------------------------------------------------- split-K reduce
__global__ void __launch_bounds__(256) k_reduce() {
    int i = blockIdx.x * 256 + threadIdx.x;          // float4 index
    if (i >= NOBS * NPAD / 4) return;
    float4 s = make_float4(0.f, 0.f, 0.f, 0.f);
#pragma unroll
    for (int sk = 0; sk < SPLITK; sk++) {
        float4 v = *(const float4*)&g_part[sk][i * 4];
        s.x += v.x; s.y += v.y; s.z += v.z; s.w += v.w;
    }
    *(float4*)&g_spred[i * 4] = s;
}

// ---------------------------------------------------------------- epilogue (block per obs)
__global__ void __launch_bounds__(256) k_epilogue(const float* __restrict__ energy,
                                                  const float* __restrict__ c_axis) {
    int obs  = blockIdx.x;
    int tid  = threadIdx.x;
    int lane = tid & 31, warp = tid >> 5;

    __shared__ __align__(16) float ca[NC];
    __shared__ float part[8];

    if (tid < NC / 4)
        *(float4*)&ca[tid * 4] = ((const float4*)(c_axis + (size_t)obs * NC))[tid];
    __syncthreads();

    float wsum = 0.0f;
    for (int p = warp; p < NPERIODS; p += 8) {
        const float* e = energy + ((size_t)obs * NPERIODS + p) * NC;
        const float4* e4 = (const float4*)e;
        float4 v = e4[lane];
        float m = fmaxf(fmaxf(v.x, v.y), fmaxf(v.z, v.w));
        if (lane < 18) {
            float4 v2 = e4[lane + 32];
            m = fmaxf(m, fmaxf(fmaxf(v2.x, v2.y), fmaxf(v2.z, v2.w)));
        }
#pragma unroll
        for (int o = 16; o; o >>= 1) m = fmaxf(m, __shfl_xor_sync(0xffffffffu, m, o));

        float cp = 1.0f / g_spred[(size_t)obs * NPAD + p];

        float4 c = ((const float4*)ca)[lane];
        int cnt = (c.x < cp) + (c.y < cp) + (c.z < cp) + (c.w < cp);
        if (lane < 18) {
            float4 c2 = ((const float4*)ca)[lane + 32];
            cnt += (c2.x < cp) + (c2.y < cp) + (c2.z < cp) + (c2.w < cp);
        }
        int idx = __reduce_add_sync(0xffffffffu, cnt);   // searchsorted-left
        idx = min(max(idx, 1), NC - 1);

        if (lane == 0) {
            float c0 = ca[idx - 1], c1 = ca[idx];
            float e0 = e[idx - 1],  e1 = e[idx];        // L1-hot, row just streamed
            float w = (cp - c0) / (c1 - c0 + 1e-12f);
            wsum += m - (e0 + w * (e1 - e0));
        }
    }

    if (lane == 0) part[warp] = wsum;
    __syncthreads();
    if (tid == 0) {
        float s = 0.0f;
        for (int i = 0; i < 8; i++) s += part[i];
        atomicAdd(&g_acc, (double)s);
    }
}

// ---------------------------------------------------------------- final scalar
__global__ void k_out(float* out) {
    out[0] = (float)(-g_acc);   // SIGMA = 1.0
}

// ---------------------------------------------------------------- launch
extern "C" void kernel_launch(void* const* d_in, const int* in_sizes, int n_in,
                              void* d_out, int out_size) {
    const float *Vs = nullptr, *A = nullptr, *energy = nullptr,
                *c_axis = nullptr, *thick = nullptr, *periods = nullptr;
    for (int i = 0; i < n_in; i++) {
        switch (in_sizes[i]) {
            case NGRID * NLAYER:          Vs      = (const float*)d_in[i]; break;
            case NOBS * NGRID:            A       = (const float*)d_in[i]; break;
            case NOBS * NPERIODS * NC:    energy  = (const float*)d_in[i]; break;
            case NOBS * NC:               c_axis  = (const float*)d_in[i]; break;
            case NLAYER:                  thick   = (const float*)d_in[i]; break;
            case NPERIODS:                periods = (const float*)d_in[i]; break;
        }
    }

    k_zero<<<1, 1>>>();
    k_weights<<<1, 64>>>(thick, periods);
    k_rcp<<<NGRID / 256, 256>>>(Vs);

    dim3 g(NOBS / BM, SPLITK);
    k_gemm<<<g, 256>>>(A);
    k_reduce<<<(NOBS * NPAD / 4 + 255) / 256, 256>>>();

    k_epilogue<<<NOBS, 256>>>(energy, c_axis);
    k_out<<<1, 1>>>((float*)d_out);
}

// round 4
// speedup vs baseline: 3.1632x; 1.0457x over previous
#include <cuda_runtime.h>
#include <cuda_bf16.h>
#include <stdint.h>

#define NGRID    8192
#define NLAYER   24
#define NPERIODS 50
#define NOBS     4096
#define NC       200
#define NPAD     64

#define BM       128
#define BN       64
#define BK       64
#define SPLITK   16
#define KCHUNK   (NGRID / SPLITK)    // 512
#define NIT      (KCHUNK / BK)       // 8
#define LDA      (BK + 8)            // 72: (4g+t) bank pattern, conflict-free
#define SMEM_GEMM ((2 * BM * LDA + 2 * BN * LDA) * 2)   // 55296 bytes

// Scratch (no allocations allowed -> __device__ globals)
__device__ __align__(16) __nv_bfloat16 g_rcpBT[NPAD * NGRID];     // B^T: [n][k]
__device__ __align__(16) float         g_part[SPLITK][NOBS * NPAD];
__device__ double                      g_acc;

// ---------------------------------------------------------------- rcp -> B^T (bf16)
// grid (NGRID/256, NPAD/16). Each block computes its own 16 periods' weights.
__global__ void __launch_bounds__(256) k_rcp(const float* __restrict__ Vs,
                                             const float* __restrict__ thick,
                                             const float* __restrict__ periods) {
    __shared__ float Wsh[16 * NLAYER];
    int pbase = blockIdx.y * 16;

    if (threadIdx.x < 16) {
        int p = pbase + threadIdx.x;
        float th[NLAYER], z[NLAYER];
        float cs = 0.0f;
        for (int l = 0; l < NLAYER; l++) {
            th[l] = thick[l];
            cs += th[l];
            z[l] = cs - 0.5f * th[l];
        }
        float w[NLAYER];
        if (p < NPERIODS) {
            float inv_ds = 3.0f / (3.0f * periods[p]);   // 1/(VREF*T/3), VREF=3
            float s = 0.0f;
            for (int l = 0; l < NLAYER; l++) {
                w[l] = expf(-z[l] * inv_ds) * th[l];
                s += w[l];
            }
            float inv_s = 1.0f / s;
            for (int l = 0; l < NLAYER; l++) w[l] *= inv_s;
        } else {
            for (int l = 0; l < NLAYER; l++) w[l] = 0.0f;
        }
        for (int l = 0; l < NLAYER; l++) Wsh[threadIdx.x * NLAYER + l] = w[l];
    }
    if (blockIdx.x == 0 && blockIdx.y == 0 && threadIdx.x == 0) g_acc = 0.0;
    __syncthreads();

    int gcell = blockIdx.x * 256 + threadIdx.x;

    float v[NLAYER];
    const float4* vp = (const float4*)(Vs + (size_t)gcell * NLAYER);
#pragma unroll
    for (int i = 0; i < 6; i++) {
        float4 f = vp[i];
        v[4*i+0] = f.x; v[4*i+1] = f.y; v[4*i+2] = f.z; v[4*i+3] = f.w;
    }
#pragma unroll
    for (int pp = 0; pp < 16; pp++) {
        int p = pbase + pp;
        __nv_bfloat16 out = __float2bfloat16(0.0f);
        if (p < NPERIODS) {
            const float* w = Wsh + pp * NLAYER;
            float s = 0.0f;
#pragma unroll
            for (int l = 0; l < NLAYER; l++) s += w[l] * v[l];
            out = __float2bfloat16(1.0f / (0.92f * s));
        }
        g_rcpBT[(size_t)p * NGRID + gcell] = out;   // coalesced along gcell
    }
}

// ---------------------------------------------------------------- GEMM (bf16 HMMA)
// Double-buffered smem, one __syncthreads per tile-loop.
__global__ void __launch_bounds__(256, 2) k_gemm(const float* __restrict__ A) {
    extern __shared__ __align__(16) __nv_bfloat16 sm[];
    __nv_bfloat16* Asb[2] = { sm,                sm + BM * LDA };
    __nv_bfloat16* Bsb[2] = { sm + 2 * BM * LDA, sm + 2 * BM * LDA + BN * LDA };

    int tid  = threadIdx.x;
    int lane = tid & 31, warp = tid >> 5;
    int wm = warp & 3, wn = warp >> 2;          // 4 x 2 warp grid
    int g = lane >> 2, t = lane & 3;
    int mBase = blockIdx.x * BM;
    int kt0   = blockIdx.y * KCHUNK;

    float acc[2][4][4];
#pragma unroll
    for (int mt = 0; mt < 2; mt++)
#pragma unroll
        for (int nt = 0; nt < 4; nt++)
#pragma unroll
            for (int i = 0; i < 4; i++) acc[mt][nt][i] = 0.0f;

    float4 aR[8], bR[2];

#define LOAD_A(KT)                                                              \
    _Pragma("unroll")                                                           \
    for (int i = 0; i < 8; i++) {                                               \
        int f = i * 256 + tid; int row = f >> 4; int c4 = f & 15;               \
        aR[i] = *(const float4*)(A + (size_t)(mBase + row) * NGRID + (KT) + c4 * 4); \
    }
#define LOAD_B(KT)                                                              \
    _Pragma("unroll")                                                           \
    for (int i = 0; i < 2; i++) {                                               \
        int f = i * 256 + tid; int row = f >> 3; int c4 = f & 7;                \
        bR[i] = *(const float4*)((const __nv_bfloat16*)g_rcpBT + (size_t)row * NGRID + (KT) + c4 * 8); \
    }
#define STORE_AB(S)                                                             \
    _Pragma("unroll")                                                           \
    for (int i = 0; i < 8; i++) {                                               \
        int f = i * 256 + tid; int row = f >> 4; int c4 = f & 15;               \
        __nv_bfloat162 lo = __float22bfloat162_rn(make_float2(aR[i].x, aR[i].y)); \
        __nv_bfloat162 hi = __float22bfloat162_rn(make_float2(aR[i].z, aR[i].w)); \
        __nv_bfloat162* dst = (__nv_bfloat162*)&Asb[S][row * LDA + c4 * 4];     \
        dst[0] = lo; dst[1] = hi;                                               \
    }                                                                           \
    _Pragma("unroll")                                                           \
    for (int i = 0; i < 2; i++) {                                               \
        int f = i * 256 + tid; int row = f >> 3; int c4 = f & 7;                \
        *(float4*)&Bsb[S][row * LDA + c4 * 8] = bR[i];                          \
    }

    LOAD_A(kt0);
    LOAD_B(kt0);
    STORE_AB(0);
    __syncthreads();

    for (int it = 0; it < NIT; it++) {
        int cur = it & 1;
        if (it + 1 < NIT) { LOAD_A(kt0 + (it + 1) * BK); LOAD_B(kt0 + (it + 1) * BK); }

        const __nv_bfloat16* As = Asb[cur];
        const __nv_bfloat16* Bs = Bsb[cur];
#pragma unroll
        for (int kk = 0; kk < BK; kk += 16) {
            uint32_t b[4][2];
#pragma unroll
            for (int nt = 0; nt < 4; nt++) {
                const uint32_t* bp = (const uint32_t*)&Bs[(wn * 32 + nt * 8 + g) * LDA + kk];
                b[nt][0] = bp[t]; b[nt][1] = bp[t + 4];
            }
#pragma unroll
            for (int mt = 0; mt < 2; mt++) {
                int r = wm * 32 + mt * 16 + g;
                const uint32_t* a0p = (const uint32_t*)&As[r * LDA + kk];
                const uint32_t* a1p = (const uint32_t*)&As[(r + 8) * LDA + kk];
                uint32_t a0 = a0p[t], a2 = a0p[t + 4];
                uint32_t a1 = a1p[t], a3 = a1p[t + 4];
#pragma unroll
                for (int nt = 0; nt < 4; nt++) {
                    asm volatile(
                        "mma.sync.aligned.m16n8k16.row.col.f32.bf16.bf16.f32 "
                        "{%0,%1,%2,%3}, {%4,%5,%6,%7}, {%8,%9}, {%0,%1,%2,%3};\n"
                        : "+f"(acc[mt][nt][0]), "+f"(acc[mt][nt][1]),
                          "+f"(acc[mt][nt][2]), "+f"(acc[mt][nt][3])
                        : "r"(a0), "r"(a1), "r"(a2), "r"(a3),
                          "r"(b[nt][0]), "r"(b[nt][1]));
                }
            }
        }

        if (it + 1 < NIT) { STORE_AB(cur ^ 1); }
        __syncthreads();
    }

    float* out = g_part[blockIdx.y];
#pragma unroll
    for (int mt = 0; mt < 2; mt++)
#pragma unroll
        for (int nt = 0; nt < 4; nt++) {
            int r0 = mBase + wm * 32 + mt * 16 + g;
            int c  = wn * 32 + nt * 8 + t * 2;
            *(float2*)&out[(size_t)r0 * NPAD + c]       = make_float2(acc[mt][nt][0], acc[mt][nt][1]);
            *(float2*)&out[(size_t)(r0 + 8) * NPAD + c] = make_float2(acc[mt][nt][2], acc[mt][nt][3]);
        }
}

// ---------------------------------------------------------------- epilogue (block per obs)
// Fuses split-K reduce (smem row) + energy max + searchsorted interp.
__global__ void __launch_bounds__(256) k_epilogue(const float* __restrict__ energy,
                                                  const float* __restrict__ c_axis) {
    int obs  = blockIdx.x;
    int tid  = threadIdx.x;
    int lane = tid & 31, warp = tid >> 5;

    __shared__ __align__(16) float ca[NC];
    __shared__ float spred_sh[NPAD];
    __shared__ float part[8];

    if (tid < NPAD) {
        float s = 0.0f;
#pragma unroll
        for (int sk = 0; sk < SPLITK; sk++)
            s += g_part[sk][(size_t)obs * NPAD + tid];
        spred_sh[tid] = s;
    }
    if (tid >= 64 && tid < 64 + NC / 4)
        *(float4*)&ca[(tid - 64) * 4] = ((const float4*)(c_axis + (size_t)obs * NC))[tid - 64];
    __syncthreads();

    float wsum = 0.0f;
    for (int p = warp; p < NPERIODS; p += 8) {
        const float* e = energy + ((size_t)obs * NPERIODS + p) * NC;
        const float4* e4 = (const float4*)e;
        float4 v = e4[lane];
        float m = fmaxf(fmaxf(v.x, v.y), fmaxf(v.z, v.w));
        if (lane < 18) {
            float4 v2 = e4[lane + 32];
            m = fmaxf(m, fmaxf(fmaxf(v2.x, v2.y), fmaxf(v2.z, v2.w)));
        }
#pragma unroll
        for (int o = 16; o; o >>= 1) m = fmaxf(m, __shfl_xor_sync(0xffffffffu, m, o));

        float cp = 1.0f / spred_sh[p];

        float4 c = ((const float4*)ca)[lane];
        int cnt = (c.x < cp) + (c.y < cp) + (c.z < cp) + (c.w < cp);
        if (lane < 18) {
            float4 c2 = ((const float4*)ca)[lane + 32];
            cnt += (c2.x < cp) + (c2.y < cp) + (c2.z < cp) + (c2.w < cp);
        }
        int idx = __reduce_add_sync(0xffffffffu, cnt);   // searchsorted-left
        idx = min(max(idx, 1), NC - 1);

        if (lane == 0) {
            float c0 = ca[idx - 1], c1 = ca[idx];
            float e0 = e[idx - 1],  e1 = e[idx];        // L1-hot, row just streamed
            float w = (cp - c0) / (c1 - c0 + 1e-12f);
            wsum += m - (e0 + w * (e1 - e0));
        }
    }

    if (lane == 0) part[warp] = wsum;
    __syncthreads();
    if (tid == 0) {
        float s = 0.0f;
        for (int i = 0; i < 8; i++) s += part[i];
        atomicAdd(&g_acc, (double)s);
    }
}

// ---------------------------------------------------------------- final scalar
__global__ void k_out(float* out) {
    out[0] = (float)(-g_acc);   // SIGMA = 1.0
}

// ---------------------------------------------------------------- launch
extern "C" void kernel_launch(void* const* d_in, const int* in_sizes, int n_in,
                              void* d_out, int out_size) {
    const float *Vs = nullptr, *A = nullptr, *energy = nullptr,
                *c_axis = nullptr, *thick = nullptr, *periods = nullptr;
    for (int i = 0; i < n_in; i++) {
        switch (in_sizes[i]) {
            case NGRID * NLAYER:          Vs      = (const float*)d_in[i]; break;
            case NOBS * NGRID:            A       = (const float*)d_in[i]; break;
            case NOBS * NPERIODS * NC:    energy  = (const float*)d_in[i]; break;
            case NOBS * NC:               c_axis  = (const float*)d_in[i]; break;
            case NLAYER:                  thick   = (const float*)d_in[i]; break;
            case NPERIODS:                periods = (const float*)d_in[i]; break;
        }
    }

    static bool attr_set = false;
    if (!attr_set) {
        cudaFuncSetAttribute(k_gemm, cudaFuncAttributeMaxDynamicSharedMemorySize, SMEM_GEMM);
        attr_set = true;
    }

    dim3 grcp(NGRID / 256, NPAD / 16);
    k_rcp<<<grcp, 256>>>(Vs, thick, periods);

    dim3 g(NOBS / BM, SPLITK);
    k_gemm<<<g, 256, SMEM_GEMM>>>(A);

    k_epilogue<<<NOBS, 256>>>(energy, c_axis);
    k_out<<<1, 1>>>((float*)d_out);
}